// round 5
// baseline (speedup 1.0000x reference)
#include <cuda_runtime.h>
#include <cuda_bf16.h>

// Sparsity_60095182405891: x[64,256,56,56] f32, NCHW.
// mask1: keep top-2 (ties >=) of |x| per 4-channel block.
// mask2: zero kept, keep top-1 (ties >=) of residual per 8-channel block.
// out = x * (mask1 | mask2).
//
// R5: final access-grain experiment. Each thread now owns TWO consecutive
// float4s per channel (32B x 8 channels): warp bursts become 1024B
// contiguous per channel, 16 front-batched LDG.128 per thread. Regs float
// (~90, no launch bounds -> no spills); occ drops to ~2 CTA/SM = 16 warps,
// still 8x the bandwidth-delay product. Tests whether deeper per-warp DRAM
// bursts move the 79.5% HBM R/W-mix plateau. Expected: neutral (+-2%).

#define C_TOT   256
#define HW      3136             // 56*56
#define GROUPS  (C_TOT / 8)      // 32
#define VEC2    (HW / 8)         // 392 float4-pairs per plane
#define TILES_PER_IMG (GROUPS * VEC2)   // 12544 = 49 * 256

__device__ __forceinline__ float second_of_4(float a0, float a1, float a2, float a3) {
    float m01 = fmaxf(a0, a1), n01 = fminf(a0, a1);
    float m23 = fmaxf(a2, a3), n23 = fminf(a2, a3);
    return fmaxf(fminf(m01, m23), fmaxf(n01, n23));
}

__global__ void __launch_bounds__(256)
sparsity_nm_kernel(const float* __restrict__ x, float* __restrict__ out) {
    int tid = blockIdx.x * 256 + threadIdx.x;   // 0 .. 12543 (exact, no tail)
    int n   = blockIdx.y;

    int g = tid / VEC2;          // 8-channel group (0..31)
    int p = tid - g * VEC2;      // which 8-float chunk within the plane

    long base = ((long)(n * C_TOT + g * 8)) * HW + (long)p * 8;

    const float4* xin = reinterpret_cast<const float4*>(x + base);
    float4*       xo  = reinterpret_cast<float4*>(out + base);

    // 16 independent vector loads, front-batched: 2 consecutive float4 per
    // channel x 8 channels (channel stride HW floats = 12544 B).
    float4 v[8][2];
#pragma unroll
    for (int c = 0; c < 8; c++) {
#pragma unroll
        for (int q = 0; q < 2; q++) {
            v[c][q] = __ldcs(xin + (long)c * (HW / 4) + q);
        }
    }

#pragma unroll
    for (int q = 0; q < 2; q++) {
        float val[8][4];
#pragma unroll
        for (int c = 0; c < 8; c++) {
            val[c][0] = v[c][q].x; val[c][1] = v[c][q].y;
            val[c][2] = v[c][q].z; val[c][3] = v[c][q].w;
        }

#pragma unroll
        for (int l = 0; l < 4; l++) {
            float a[8];
#pragma unroll
            for (int c = 0; c < 8; c++) a[c] = fabsf(val[c][l]);

            float thr0 = second_of_4(a[0], a[1], a[2], a[3]);
            float thr1 = second_of_4(a[4], a[5], a[6], a[7]);

            bool  m1[8];
            float r[8];
            float rmax = 0.0f;
#pragma unroll
            for (int c = 0; c < 8; c++) {
                float thr = (c < 4) ? thr0 : thr1;
                m1[c] = (a[c] >= thr);
                r[c]  = m1[c] ? 0.0f : a[c];
                rmax  = fmaxf(rmax, r[c]);
            }

#pragma unroll
            for (int c = 0; c < 8; c++) {
                bool keep = m1[c] || (r[c] >= rmax);
                val[c][l] = keep ? val[c][l] : 0.0f;
            }
        }

#pragma unroll
        for (int c = 0; c < 8; c++) {
            v[c][q].x = val[c][0]; v[c][q].y = val[c][1];
            v[c][q].z = val[c][2]; v[c][q].w = val[c][3];
        }
    }

    // Streaming stores: 2 consecutive float4 per channel
#pragma unroll
    for (int c = 0; c < 8; c++) {
#pragma unroll
        for (int q = 0; q < 2; q++) {
            __stcs(xo + (long)c * (HW / 4) + q, v[c][q]);
        }
    }
}

extern "C" void kernel_launch(void* const* d_in, const int* in_sizes, int n_in,
                              void* d_out, int out_size) {
    const float* x = (const float*)d_in[0];
    float* out = (float*)d_out;
    dim3 grid(TILES_PER_IMG / 256, 64);   // (49, 64)
    sparsity_nm_kernel<<<grid, 256>>>(x, out);
}

// round 6
// speedup vs baseline: 1.1521x; 1.1521x over previous
#include <cuda_runtime.h>
#include <cuda_bf16.h>

// Sparsity_60095182405891: x[64,256,56,56] f32, NCHW.
// mask1: keep top-2 (ties >=) of |x| per 4-channel block.
// mask2: zero kept, keep top-1 (ties >=) of residual per 8-channel block.
// out = x * (mask1 | mask2).
//
// FINAL (R6 = R2/R4 configuration, converged):
//  - Per-thread tile: 1 float4 x 8 channels -> 8 front-batched LDG.128
//    (MLP=8), regs=50, no spills, 5 CTA/SM (40 warps).
//  - Streaming __ldcs/__stcs (one-pass data).
//  - Measured wall: 6.30 TB/s HBM (79.5% of spec) = R/W-mix ceiling.
//    Falsified alternatives: occ-cap 6 CTA/SM (spills, 74.7%, R3);
//    2x tile / 16 LDG (regs 76, spills, 64.8%, R5); cache-policy (neutral, R2).
//    Traffic (205MB R + 205MB W) is irreducible; compute pipes idle.

#define C_TOT   256
#define HW      3136            // 56*56
#define GROUPS  (C_TOT / 8)     // 32
#define VEC     (HW / 4)        // 784
#define TILES_PER_IMG (GROUPS * VEC)   // 25088 = 98 * 256

__device__ __forceinline__ float second_of_4(float a0, float a1, float a2, float a3) {
    // 2nd largest of 4 (tournament): max( min(max01, max23), max(min01, min23) )
    float m01 = fmaxf(a0, a1), n01 = fminf(a0, a1);
    float m23 = fmaxf(a2, a3), n23 = fminf(a2, a3);
    return fmaxf(fminf(m01, m23), fmaxf(n01, n23));
}

__global__ void __launch_bounds__(256)
sparsity_nm_kernel(const float* __restrict__ x, float* __restrict__ out) {
    int tid = blockIdx.x * 256 + threadIdx.x;   // 0 .. 25087 (exact, no tail)
    int n   = blockIdx.y;

    int g = tid / VEC;          // 8-channel group (0..31)
    int p = tid - g * VEC;      // float4 index within the 56x56 plane

    long base = ((long)(n * C_TOT + g * 8)) * HW + (long)p * 4;

    const float4* xin = reinterpret_cast<const float4*>(x + base);
    float4*       xo  = reinterpret_cast<float4*>(out + base);

    // 8 independent strided vector loads (stride HW floats = 12544 B),
    // streaming (evict-first) - data is touched exactly once.
    float4 v[8];
#pragma unroll
    for (int c = 0; c < 8; c++) {
        v[c] = __ldcs(xin + (long)c * (HW / 4));
    }

    float val[8][4];
#pragma unroll
    for (int c = 0; c < 8; c++) {
        val[c][0] = v[c].x; val[c][1] = v[c].y;
        val[c][2] = v[c].z; val[c][3] = v[c].w;
    }

#pragma unroll
    for (int l = 0; l < 4; l++) {
        float a[8];
#pragma unroll
        for (int c = 0; c < 8; c++) a[c] = fabsf(val[c][l]);

        // mask1: top-2 (ties kept) within each 4-channel block
        float thr0 = second_of_4(a[0], a[1], a[2], a[3]);
        float thr1 = second_of_4(a[4], a[5], a[6], a[7]);

        bool  m1[8];
        float r[8];
        float rmax = 0.0f;
#pragma unroll
        for (int c = 0; c < 8; c++) {
            float thr = (c < 4) ? thr0 : thr1;
            m1[c] = (a[c] >= thr);
            r[c]  = m1[c] ? 0.0f : a[c];
            rmax  = fmaxf(rmax, r[c]);
        }

        // mask2: top-1 (ties kept) of residual over the 8-block; OR with mask1
#pragma unroll
        for (int c = 0; c < 8; c++) {
            bool keep = m1[c] || (r[c] >= rmax);
            val[c][l] = keep ? val[c][l] : 0.0f;
        }
    }

    // Repack and streaming-store (evict-first; output never re-read)
#pragma unroll
    for (int c = 0; c < 8; c++) {
        float4 o;
        o.x = val[c][0]; o.y = val[c][1]; o.z = val[c][2]; o.w = val[c][3];
        __stcs(xo + (long)c * (HW / 4), o);
    }
}

extern "C" void kernel_launch(void* const* d_in, const int* in_sizes, int n_in,
                              void* d_out, int out_size) {
    const float* x = (const float*)d_in[0];
    float* out = (float*)d_out;
    dim3 grid(TILES_PER_IMG / 256, 64);   // (98, 64)
    sparsity_nm_kernel<<<grid, 256>>>(x, out);
}

// round 7
// speedup vs baseline: 1.1579x; 1.0050x over previous
#include <cuda_runtime.h>
#include <cuda_bf16.h>

// Sparsity_60095182405891: x[64,256,56,56] f32, NCHW.
// mask1: keep top-2 (ties >=) of |x| per 4-channel block.
// mask2: zero kept, keep top-1 (ties >=) of residual per 8-channel block.
// out = x * (mask1 | mask2).
//
// CONVERGED FINAL. Operating point: 1 float4 x 8 channels per thread
// (8 front-batched LDG.128, MLP=8), regs=50 no spills, 5 CTA/SM, streaming
// __ldcs/__stcs. Measured 56.2-56.7us kernel, 6.29-6.34 TB/s HBM (79-80%
// of spec) across 4 runs = the HBM3e 1:1 R/W-mix ceiling.
// Falsified: occ-cap (spills, -12%), 2x tile/MLP16 (spills+occ, -24%),
// cache policy (neutral), grid shape (neutral). Traffic (205MB R + 205MB W,
// f32 in/out) is irreducible; all compute pipes <1% except alu (addressing).

#define C_TOT   256
#define HW      3136            // 56*56
#define GROUPS  (C_TOT / 8)     // 32
#define VEC     (HW / 4)        // 784
#define TILES_PER_IMG (GROUPS * VEC)   // 25088 = 98 * 256

__device__ __forceinline__ float second_of_4(float a0, float a1, float a2, float a3) {
    // 2nd largest of 4 (tournament): max( min(max01, max23), max(min01, min23) )
    float m01 = fmaxf(a0, a1), n01 = fminf(a0, a1);
    float m23 = fmaxf(a2, a3), n23 = fminf(a2, a3);
    return fmaxf(fminf(m01, m23), fmaxf(n01, n23));
}

__global__ void __launch_bounds__(256)
sparsity_nm_kernel(const float* __restrict__ x, float* __restrict__ out) {
    int tid = blockIdx.x * 256 + threadIdx.x;   // 0 .. 25087 (exact, no tail)
    int n   = blockIdx.y;

    int g = tid / VEC;          // 8-channel group (0..31)
    int p = tid - g * VEC;      // float4 index within the 56x56 plane

    long base = ((long)(n * C_TOT + g * 8)) * HW + (long)p * 4;

    const float4* xin = reinterpret_cast<const float4*>(x + base);
    float4*       xo  = reinterpret_cast<float4*>(out + base);

    // 8 independent strided vector loads (stride HW floats = 12544 B),
    // streaming (evict-first) - data is touched exactly once.
    float4 v[8];
#pragma unroll
    for (int c = 0; c < 8; c++) {
        v[c] = __ldcs(xin + (long)c * (HW / 4));
    }

    float val[8][4];
#pragma unroll
    for (int c = 0; c < 8; c++) {
        val[c][0] = v[c].x; val[c][1] = v[c].y;
        val[c][2] = v[c].z; val[c][3] = v[c].w;
    }

#pragma unroll
    for (int l = 0; l < 4; l++) {
        float a[8];
#pragma unroll
        for (int c = 0; c < 8; c++) a[c] = fabsf(val[c][l]);

        // mask1: top-2 (ties kept) within each 4-channel block
        float thr0 = second_of_4(a[0], a[1], a[2], a[3]);
        float thr1 = second_of_4(a[4], a[5], a[6], a[7]);

        bool  m1[8];
        float r[8];
        float rmax = 0.0f;
#pragma unroll
        for (int c = 0; c < 8; c++) {
            float thr = (c < 4) ? thr0 : thr1;
            m1[c] = (a[c] >= thr);
            r[c]  = m1[c] ? 0.0f : a[c];
            rmax  = fmaxf(rmax, r[c]);
        }

        // mask2: top-1 (ties kept) of residual over the 8-block; OR with mask1
#pragma unroll
        for (int c = 0; c < 8; c++) {
            bool keep = m1[c] || (r[c] >= rmax);
            val[c][l] = keep ? val[c][l] : 0.0f;
        }
    }

    // Repack and streaming-store (evict-first; output never re-read)
#pragma unroll
    for (int c = 0; c < 8; c++) {
        float4 o;
        o.x = val[c][0]; o.y = val[c][1]; o.z = val[c][2]; o.w = val[c][3];
        __stcs(xo + (long)c * (HW / 4), o);
    }
}

extern "C" void kernel_launch(void* const* d_in, const int* in_sizes, int n_in,
                              void* d_out, int out_size) {
    const float* x = (const float*)d_in[0];
    float* out = (float*)d_out;
    dim3 grid(TILES_PER_IMG / 256, 64);   // (98, 64)
    sparsity_nm_kernel<<<grid, 256>>>(x, out);
}